// round 1
// baseline (speedup 1.0000x reference)
#include <cuda_runtime.h>

#define HH 4096
#define WW 4096
#define TW 256          // output columns per block (128 threads x 2 cols)
#define SEG 64          // output rows per block
#define NT 128
#define HALO 7
#define PADW (TW + 2*HALO)                 // 270
#define NCHUNK ((SEG + 2*HALO + 15) / 16)  // 5 chunks of 16 prefix-rows

// c_k = 1/(7*k^2) for k = 3,5,7,9,11,13,15
#define CK1 (1.0f/63.0f)
#define CK2 (1.0f/175.0f)
#define CK3 (1.0f/343.0f)
#define CK4 (1.0f/567.0f)
#define CK5 (1.0f/847.0f)
#define CK6 (1.0f/1183.0f)
#define CK7 (1.0f/1575.0f)

template<bool FIRST>
__device__ __forceinline__ void run_chunk(
    int tbase, int y0, int x0, int tid,
    const float* __restrict__ x, const float* __restrict__ mp,
    float* __restrict__ out,
    float2 (*Crow)[PADW/2 + 1],
    float (&acc0)[16], float (&acc1)[16],
    float& cs0, float& cs1, float& cs2,
    int g0, int g1, int g2)
{
    const float CK[7] = {CK1, CK2, CK3, CK4, CK5, CK6, CK7};
#pragma unroll
    for (int i = 0; i < 16; i++) {
        int t  = tbase + i;                       // absolute prefix-row index
        int ry = t < 0 ? 0 : (t >= HH ? HH - 1 : t);   // replicate pad (rows)
        const float* xr = x + (size_t)ry * WW;

        // accumulate column prefix sums in registers, publish to shared
        float v0 = __ldg(xr + g0);
        float v1 = __ldg(xr + g1);
        float v2 = (tid < PADW - 2*NT) ? __ldg(xr + g2) : 0.0f;
        cs0 += v0; cs1 += v1; cs2 += v2;

        float* Cf = (float*)Crow[t & 1];          // double buffer -> 1 bar/row
        Cf[tid]        = cs0;
        Cf[tid + NT]   = cs1;
        if (tid < PADW - 2*NT) Cf[tid + 2*NT] = cs2;
        __syncthreads();

        // read 16-float window covering both of this thread's columns
        float a[16];
        const float2* C2 = Crow[t & 1];
#pragma unroll
        for (int q = 0; q < 8; q++) {
            float2 w = C2[tid + q];
            a[2*q] = w.x; a[2*q + 1] = w.y;
        }

        // incremental horizontal window sums H_3..H_15 of the prefix row,
        // scatter +c_k*H_k to row (t-r), -c_k*H_k to row (t+r+1)
        float h0 = 0.0f;
#pragma unroll
        for (int r = 1; r <= 7; r++) {
            if (r == 1) h0 = a[6] + a[7] + a[8];
            else        h0 += a[7 - r] + a[7 + r];
            float h1 = h0 + a[8 + r] - a[7 - r];
            float c  = CK[r - 1];
            if (!FIRST || i >= 7 + r) {           // target row t-r >= y0
                int sp = (i - r + 9) & 15;
                acc0[sp] += c * h0;
                acc1[sp] += c * h1;
            }
            if (!FIRST || i + r >= 6) {           // target row t+r+1 >= y0
                int sm = (i + r + 10) & 15;
                acc0[sm] -= c * h0;
                acc1[sm] -= c * h1;
            }
        }

        // row y = t-7 received its last contribution this iteration
        int yr = t - 7;
        if ((!FIRST || i >= 14) && yr < y0 + SEG) {
            int s   = (i + 2) & 15;
            int col = x0 + 2 * tid;
            size_t off = (size_t)yr * WW + col;
            float2 m = *(const float2*)(mp + off);
            float2 o;
            o.x = acc0[s] * m.x;
            o.y = acc1[s] * m.y;
            *(float2*)(out + off) = o;
            acc0[s] = 0.0f; acc1[s] = 0.0f;
        }
    }
}

__global__ __launch_bounds__(NT)
void meanconv_kernel(const float* __restrict__ x,
                     const float* __restrict__ mp,
                     float* __restrict__ out)
{
    __shared__ float2 Crow[2][PADW/2 + 1];        // double-buffered prefix row

    const int tid = threadIdx.x;
    const int x0  = blockIdx.x * TW;
    const int y0  = blockIdx.y * SEG;

    float acc0[16], acc1[16];
#pragma unroll
    for (int i = 0; i < 16; i++) { acc0[i] = 0.0f; acc1[i] = 0.0f; }

    // replicate pad (cols): clamped gather indices, fixed per block
    int g0 = x0 - HALO + tid;
    int g1 = g0 + NT;
    int g2 = g0 + 2*NT;
    g0 = min(max(g0, 0), WW - 1);
    g1 = min(max(g1, 0), WW - 1);
    g2 = min(max(g2, 0), WW - 1);

    float cs0 = 0.0f, cs1 = 0.0f, cs2 = 0.0f;

    run_chunk<true>(y0 - 7, y0, x0, tid, x, mp, out, Crow, acc0, acc1,
                    cs0, cs1, cs2, g0, g1, g2);
#pragma unroll 1
    for (int c = 1; c < NCHUNK; c++) {
        run_chunk<false>(y0 - 7 + 16 * c, y0, x0, tid, x, mp, out, Crow,
                         acc0, acc1, cs0, cs1, cs2, g0, g1, g2);
    }
}

extern "C" void kernel_launch(void* const* d_in, const int* in_sizes, int n_in,
                              void* d_out, int out_size)
{
    const float* x  = (const float*)d_in[0];
    const float* mp = (const float*)d_in[1];
    float* out      = (float*)d_out;
    dim3 grid(WW / TW, HH / SEG);
    meanconv_kernel<<<grid, NT>>>(x, mp, out);
}

// round 2
// speedup vs baseline: 1.3615x; 1.3615x over previous
#include <cuda_runtime.h>

#define HH 4096
#define WW 4096
#define TW 256          // output columns per block (128 threads x 2 cols)
#define SEG 64          // output rows per block
#define NT 128
#define HALO 7
#define PADW (TW + 2*HALO)                 // 270 valid floats per prefix row
#define SSTR 272                            // shared row stride (float2-aligned)

// c_k = 1/(7*k^2) for k = 3,5,7,9,11,13,15
#define CK1 (1.0f/63.0f)
#define CK2 (1.0f/175.0f)
#define CK3 (1.0f/343.0f)
#define CK4 (1.0f/567.0f)
#define CK5 (1.0f/847.0f)
#define CK6 (1.0f/1183.0f)
#define CK7 (1.0f/1575.0f)

// One 16-prefix-row chunk = 4 subchunks of 4 rows.
// Per subchunk: prefetch next subchunk's 12 LDGs, publish 4 prefix rows to
// shared (double-buffered), 1 barrier, then window math for 4 rows.
template<bool FIRST>
__device__ __forceinline__ void run_chunk(
    int tbase, int y0, int x0, int tid,
    const float* __restrict__ x, const float* __restrict__ mp,
    float* __restrict__ out,
    float (*sbuf)[4 * SSTR],
    float (&acc0)[16], float (&acc1)[16],
    float& cs0, float& cs1, float& cs2,
    int g0, int g1, int g2,
    float3 (&vcur)[4])
{
    const float CK[7] = {CK1, CK2, CK3, CK4, CK5, CK6, CK7};
#pragma unroll
    for (int s = 0; s < 4; s++) {
        // ---- prefetch loads for the NEXT subchunk (independent of shared) ----
        float3 vnext[4];
        {
            int tn = tbase + 4 * (s + 1);
#pragma unroll
            for (int j = 0; j < 4; j++) {
                int t  = tn + j;
                int ry = min(max(t, 0), HH - 1);     // replicate pad (rows)
                const float* xr = x + (size_t)ry * WW;
                vnext[j].x = __ldg(xr + g0);
                vnext[j].y = __ldg(xr + g1);
                vnext[j].z = __ldg(xr + g2);
            }
        }

        // ---- publish 4 prefix rows for the CURRENT subchunk ----
        float* S = sbuf[s & 1];
#pragma unroll
        for (int j = 0; j < 4; j++) {
            cs0 += vcur[j].x; cs1 += vcur[j].y; cs2 += vcur[j].z;
            S[j * SSTR + tid]      = cs0;
            S[j * SSTR + NT + tid] = cs1;
            if (tid < PADW - 2 * NT) S[j * SSTR + 2 * NT + tid] = cs2;
        }
        __syncthreads();

        // ---- window math for 4 rows ----
#pragma unroll
        for (int j = 0; j < 4; j++) {
            const int i = 4 * s + j;                 // compile-time in chunk
            int t = tbase + i;

            float a[16];
            const float2* C2 = (const float2*)(S + j * SSTR);
#pragma unroll
            for (int q = 0; q < 8; q++) {
                float2 w = C2[tid + q];
                a[2 * q] = w.x; a[2 * q + 1] = w.y;
            }

            // incremental horizontal window sums H_3..H_15, ring scatter
            float h0 = 0.0f;
#pragma unroll
            for (int r = 1; r <= 7; r++) {
                if (r == 1) h0 = a[6] + a[7] + a[8];
                else        h0 += a[7 - r] + a[7 + r];
                float h1 = h0 + a[8 + r] - a[7 - r];
                float c  = CK[r - 1];
                if (!FIRST || i >= 7 + r) {          // target row t-r >= y0
                    int sp = (i - r + 9) & 15;
                    acc0[sp] += c * h0;
                    acc1[sp] += c * h1;
                }
                if (!FIRST || i + r >= 6) {          // target row t+r+1 >= y0
                    int sm = (i + r + 10) & 15;
                    acc0[sm] -= c * h0;
                    acc1[sm] -= c * h1;
                }
            }

            // row y = t-7 is complete after this prefix row
            int yr = t - 7;
            if ((!FIRST || i >= 14) && yr < y0 + SEG) {
                int sl  = (i + 2) & 15;
                size_t off = (size_t)yr * WW + x0 + 2 * tid;
                float2 m = *(const float2*)(mp + off);
                float2 o;
                o.x = acc0[sl] * m.x;
                o.y = acc1[sl] * m.y;
                *(float2*)(out + off) = o;
                acc0[sl] = 0.0f; acc1[sl] = 0.0f;
            }
        }

#pragma unroll
        for (int j = 0; j < 4; j++) vcur[j] = vnext[j];
    }
}

__global__ __launch_bounds__(NT)
void meanconv_kernel(const float* __restrict__ x,
                     const float* __restrict__ mp,
                     float* __restrict__ out)
{
    __shared__ float sbuf[2][4 * SSTR];             // double-buffered 4-row tiles

    const int tid = threadIdx.x;
    const int x0  = blockIdx.x * TW;
    const int y0  = blockIdx.y * SEG;

    float acc0[16], acc1[16];
#pragma unroll
    for (int i = 0; i < 16; i++) { acc0[i] = 0.0f; acc1[i] = 0.0f; }

    // replicate pad (cols): clamped gather indices, fixed per block
    int g0 = x0 - HALO + tid;
    int g1 = g0 + NT;
    int g2 = g0 + 2 * NT;
    g0 = min(max(g0, 0), WW - 1);
    g1 = min(max(g1, 0), WW - 1);
    g2 = min(max(g2, 0), WW - 1);

    float cs0 = 0.0f, cs1 = 0.0f, cs2 = 0.0f;

    // prologue: loads for chunk 0, subchunk 0
    float3 vcur[4];
#pragma unroll
    for (int j = 0; j < 4; j++) {
        int t  = y0 - 7 + j;
        int ry = min(max(t, 0), HH - 1);
        const float* xr = x + (size_t)ry * WW;
        vcur[j] = make_float3(__ldg(xr + g0), __ldg(xr + g1), __ldg(xr + g2));
    }

    run_chunk<true>(y0 - 7, y0, x0, tid, x, mp, out, sbuf, acc0, acc1,
                    cs0, cs1, cs2, g0, g1, g2, vcur);
#pragma unroll 1
    for (int c = 1; c < 5; c++) {
        run_chunk<false>(y0 - 7 + 16 * c, y0, x0, tid, x, mp, out, sbuf,
                         acc0, acc1, cs0, cs1, cs2, g0, g1, g2, vcur);
    }
}

extern "C" void kernel_launch(void* const* d_in, const int* in_sizes, int n_in,
                              void* d_out, int out_size)
{
    const float* x  = (const float*)d_in[0];
    const float* mp = (const float*)d_in[1];
    float* out      = (float*)d_out;
    dim3 grid(WW / TW, HH / SEG);
    meanconv_kernel<<<grid, NT>>>(x, mp, out);
}